// round 6
// baseline (speedup 1.0000x reference)
#include <cuda_runtime.h>
#include <cuda_bf16.h>
#include <cstdint>

#define GR 8
#define BATCH 32
#define TT 512
#define ROWS 384          // 3 * 128
#define PADW 386          // phase-1 weight smem row stride (floats)
#define XROW 132          // phase-1 x smem row stride (floats)

typedef unsigned long long ull;

// 201 MB scratch for gx[t][g][o][b]
__device__ float g_gx[(size_t)TT * GR * ROWS * BATCH];

__device__ __forceinline__ ull pk(float lo, float hi) {
    ull r;
    asm("mov.b64 %0, {%1, %2};" : "=l"(r) : "f"(lo), "f"(hi));
    return r;
}
__device__ __forceinline__ float2 up(ull v) {
    float2 r;
    asm("mov.b64 {%0, %1}, %2;" : "=f"(r.x), "=f"(r.y) : "l"(v));
    return r;
}
__device__ __forceinline__ void fma2(ull& d, ull a, ull b) {
    asm("fma.rn.f32x2 %0, %1, %2, %0;" : "+l"(d) : "l"(a), "l"(b));
}
__device__ __forceinline__ float sigm(float x) {
    return __fdividef(1.0f, 1.0f + __expf(-x));
}
__device__ __forceinline__ float tanh_(float x) {
    return 1.0f - __fdividef(2.0f, __expf(2.0f * x) + 1.0f);
}
__device__ __forceinline__ float hadd(ull v) {
    float2 u = up(v);
    return u.x + u.y;
}
__device__ __forceinline__ unsigned sptr(const void* p) {
    return (unsigned)__cvta_generic_to_shared(p);
}
__device__ __forceinline__ void cpa8(unsigned d, const void* s) {
    asm volatile("cp.async.ca.shared.global [%0], [%1], 8;" :: "r"(d), "l"(s));
}
__device__ __forceinline__ void cpa16(unsigned d, const void* s) {
    asm volatile("cp.async.cg.shared.global [%0], [%1], 16;" :: "r"(d), "l"(s));
}
__device__ __forceinline__ void cpcommit() { asm volatile("cp.async.commit_group;" ::: "memory"); }
__device__ __forceinline__ void cpwait0()  { asm volatile("cp.async.wait_group 0;" ::: "memory"); }
__device__ __forceinline__ void cpwait1()  { asm volatile("cp.async.wait_group 1;" ::: "memory"); }

// ============================================================================
// Phase 1: gx[t][g][o][b] (unchanged from R4: 313us, ~65% of its fma floor)
// ============================================================================
__global__ void __launch_bounds__(512, 1)
gx_kernel(const float* __restrict__ x,
          const float* __restrict__ W_ih,
          const float* __restrict__ b_ih)
{
    extern __shared__ float sm[];
    float* Ws = sm;                       // [128][PADW]  W[k][o]
    float* Xs = sm + 128 * PADW;          // [2][32][XROW] x[b][k]

    const int g  = blockIdx.x & 7;
    const int tb = blockIdx.x >> 3;
    const int tid = threadIdx.x;

    const float* Wg = W_ih + (size_t)g * ROWS * 128;
    for (int idx = tid; idx < ROWS * 128; idx += 512) {
        int o = idx >> 7, k = idx & 127;
        Ws[k * PADW + o] = Wg[idx];
    }

    const int w    = tid >> 5;
    const int lane = tid & 31;
    const int rsub = lane >> 3;
    const int bq   = lane & 7;
    const int ro   = w * 24 + rsub * 6;

    float bias[6];
#pragma unroll
    for (int i = 0; i < 6; i++) bias[i] = b_ih[g * ROWS + ro + i];

    {
        const int t0 = tb * 32;
#pragma unroll
        for (int r = 0; r < 2; r++) {
            int c = tid + r * 512;
            int b = c >> 5, kq = c & 31;
            cpa16(sptr(Xs + b * XROW + kq * 4),
                  x + ((size_t)b * TT + t0) * 1024 + g * 128 + kq * 4);
        }
    }
    cpcommit();

    for (int tt = 0; tt < 32; tt++) {
        const int t = tb * 32 + tt;
        const float* Xc = Xs + (tt & 1) * (32 * XROW);

        cpwait0();
        __syncthreads();

        if (tt < 31) {
            float* Xn = Xs + ((tt + 1) & 1) * (32 * XROW);
#pragma unroll
            for (int r = 0; r < 2; r++) {
                int c = tid + r * 512;
                int b = c >> 5, kq = c & 31;
                cpa16(sptr(Xn + b * XROW + kq * 4),
                      x + ((size_t)b * TT + t + 1) * 1024 + g * 128 + kq * 4);
            }
        }
        cpcommit();

        ull acc[3][4];
#pragma unroll
        for (int p = 0; p < 3; p++) {
            ull binit = pk(bias[2 * p], bias[2 * p + 1]);
#pragma unroll
            for (int i = 0; i < 4; i++) acc[p][i] = binit;
        }

#pragma unroll 4
        for (int k = 0; k < 128; k++) {
            const float* wb = Ws + k * PADW + ro;
            ull w0 = *(const ull*)(wb);
            ull w1 = *(const ull*)(wb + 2);
            ull w2 = *(const ull*)(wb + 4);
            float x0 = Xc[(bq     ) * XROW + k];
            float x1 = Xc[(bq +  8) * XROW + k];
            float x2 = Xc[(bq + 16) * XROW + k];
            float x3 = Xc[(bq + 24) * XROW + k];
            ull d0 = pk(x0, x0), d1 = pk(x1, x1), d2 = pk(x2, x2), d3 = pk(x3, x3);
            fma2(acc[0][0], w0, d0); fma2(acc[0][1], w0, d1);
            fma2(acc[0][2], w0, d2); fma2(acc[0][3], w0, d3);
            fma2(acc[1][0], w1, d0); fma2(acc[1][1], w1, d1);
            fma2(acc[1][2], w1, d2); fma2(acc[1][3], w1, d3);
            fma2(acc[2][0], w2, d0); fma2(acc[2][1], w2, d1);
            fma2(acc[2][2], w2, d2); fma2(acc[2][3], w2, d3);
        }

        float* outp = g_gx + ((size_t)t * GR + g) * ROWS * BATCH;
#pragma unroll
        for (int p = 0; p < 3; p++) {
#pragma unroll
            for (int i = 0; i < 4; i++) {
                float2 u = up(acc[p][i]);
                outp[(ro + 2 * p)     * BATCH + bq + 8 * i] = u.x;
                outp[(ro + 2 * p + 1) * BATCH + bq + 8 * i] = u.y;
            }
        }
    }
}

// ============================================================================
// Phase 2: recurrence, output-row-parallel. 128 CTAs = (g, bp: 2 batches),
// 768 threads: o = tid>>1 (output row, one gate), kh = tid&1 (k-half of 64).
// Weights: 32 f32x2 k-pairs in regs (64 regs -> big slack under the 85 cap).
// K-loop: broadcast LDS.128 of h + fma2 only — NO shfl, NO weight loads.
// Preacts exchanged via padded smem (stride 6 -> conflict-free); 128 gate
// threads do gates for both batches; threads 128..511 stage gx (cp.async
// ring) during the gate phase. Ping-pong h. 2 barriers/step.
// ============================================================================
__global__ void __launch_bounds__(768, 1)
gru_kernel(const float* __restrict__ state,
           const float* __restrict__ W_hh,
           const float* __restrict__ b_hh,
           float* __restrict__ out)
{
    __shared__ __align__(16) float Hb0[2][128];
    __shared__ __align__(16) float Hb1[2][128];
    __shared__ __align__(16) float P[ROWS * 6];      // [o][kh*2 + b], stride 6
    __shared__ __align__(16) float Gs[3][ROWS * 2];  // gx ring [buf][o*2 + b]

    const int g   = blockIdx.x >> 4;
    const int bp  = blockIdx.x & 15;
    const int tid = threadIdx.x;
    const int o   = tid >> 1;        // 0..383
    const int kh  = tid & 1;         // 0..1
    const int b0  = bp * 2;

    // ---- weights: row o, k in [kh*64, kh*64+64), as 32 f32x2 pairs ----
    ull w[32];
    {
        const float* wrow = W_hh + (size_t)g * ROWS * 128 + (size_t)o * 128 + kh * 64;
#pragma unroll
        for (int i = 0; i < 16; i++) {
            ulonglong2 v = *(const ulonglong2*)(wrow + i * 4);
            w[2 * i] = v.x; w[2 * i + 1] = v.y;
        }
    }

    // gate-thread constants (threads 0..127, j = tid)
    float bhr = 0.f, bhz = 0.f, bhn = 0.f;
    if (tid < 128) {
        bhr = b_hh[g * ROWS + tid];
        bhz = b_hh[g * ROWS + 128 + tid];
        bhn = b_hh[g * ROWS + 256 + tid];
        Hb0[0][tid] = state[((size_t)g * 32 + b0) * 128 + tid];
        Hb1[0][tid] = state[((size_t)g * 32 + b0 + 1) * 128 + tid];
    }

    const size_t stride_t = (size_t)GR * ROWS * BATCH;
    const float* gx0 = g_gx + (size_t)g * ROWS * BATCH + b0;

    // gx staging owned by threads 128..511 (row = tid-128)
    const int crow = tid - 128;
    const bool is_cp = (crow >= 0) && (crow < ROWS);
    const float* gxt = gx0 + (size_t)(is_cp ? crow : 0) * BATCH;

    if (is_cp) cpa8(sptr(&Gs[0][crow * 2]), gxt);
    cpcommit();
    if (is_cp) cpa8(sptr(&Gs[1][crow * 2]), gxt + stride_t);
    cpcommit();
    gxt += 2 * stride_t;
    cpwait1();
    __syncthreads();

    float* outp = out + ((size_t)b0 * TT) * 1024 + g * 128 + tid;  // gate threads
    const int khoff = kh * 64;

    int p = 0, cb = 0;

    for (int t = 0; t < TT; t++) {
        const float* H0 = Hb0[p];
        const float* H1 = Hb1[p];

        ull a0 = 0, a1 = 0;
#pragma unroll
        for (int i = 0; i < 16; i++) {
            ulonglong2 h0 = *(const ulonglong2*)(H0 + khoff + i * 4);
            ulonglong2 h1 = *(const ulonglong2*)(H1 + khoff + i * 4);
            fma2(a0, w[2 * i],     h0.x);
            fma2(a1, w[2 * i],     h1.x);
            fma2(a0, w[2 * i + 1], h0.y);
            fma2(a1, w[2 * i + 1], h1.y);
        }

        // preact partials -> smem
        *(float2*)(P + o * 6 + kh * 2) = make_float2(hadd(a0), hadd(a1));
        __syncthreads();   // preacts ready; h[p] reads complete

        const int np = p ^ 1;
        if (tid < 128) {
            const int j = tid;
            float2 pr0 = *(const float2*)(P + (j)       * 6);
            float2 pr1 = *(const float2*)(P + (j)       * 6 + 2);
            float2 pz0 = *(const float2*)(P + (128 + j) * 6);
            float2 pz1 = *(const float2*)(P + (128 + j) * 6 + 2);
            float2 pn0 = *(const float2*)(P + (256 + j) * 6);
            float2 pn1 = *(const float2*)(P + (256 + j) * 6 + 2);
            const float* Gc = Gs[cb];
            float2 gr = *(const float2*)(Gc + (j)       * 2);
            float2 gz = *(const float2*)(Gc + (128 + j) * 2);
            float2 gn = *(const float2*)(Gc + (256 + j) * 2);
            float h0old = Hb0[p][j];
            float h1old = Hb1[p][j];

            float r0 = sigm(gr.x + pr0.x + pr1.x + bhr);
            float r1 = sigm(gr.y + pr0.y + pr1.y + bhr);
            float z0 = sigm(gz.x + pz0.x + pz1.x + bhz);
            float z1 = sigm(gz.y + pz0.y + pz1.y + bhz);
            float n0 = tanh_(gn.x + r0 * (pn0.x + pn1.x + bhn));
            float n1 = tanh_(gn.y + r1 * (pn0.y + pn1.y + bhn));
            float h0n = n0 + z0 * (h0old - n0);
            float h1n = n1 + z1 * (h1old - n1);

            Hb0[np][j] = h0n;
            Hb1[np][j] = h1n;
            outp[0]         = h0n;
            outp[TT * 1024] = h1n;
            outp += 1024;
        } else if (is_cp) {
            // stage gx for t+2 into buffer (cb+2)%3
            int nb = cb + 2; if (nb >= 3) nb -= 3;
            if (t + 2 < TT)
                cpa8(sptr(&Gs[nb][crow * 2]), gxt);
            gxt += stride_t;
        }
        cpcommit();
        cpwait1();          // group for t+1 complete
        __syncthreads();    // h[np] + Gs[cb+1] visible
        p = np;
        cb = cb + 1; if (cb >= 3) cb -= 3;
    }

    // h_out[g][b][j] appended after y
    if (tid < 128) {
        float* hop = out + (size_t)BATCH * TT * 1024;
        hop[((size_t)g * 32 + b0) * 128 + tid]     = Hb0[p][tid];
        hop[((size_t)g * 32 + b0 + 1) * 128 + tid] = Hb1[p][tid];
    }
}

extern "C" void kernel_launch(void* const* d_in, const int* in_sizes, int n_in,
                              void* d_out, int out_size)
{
    const float* x     = (const float*)d_in[0];
    const float* state = (const float*)d_in[1];
    const float* W_ih  = (const float*)d_in[2];
    const float* W_hh  = (const float*)d_in[3];
    const float* b_ih  = (const float*)d_in[4];
    const float* b_hh  = (const float*)d_in[5];
    float* out = (float*)d_out;

    const int smem1 = (128 * PADW + 2 * 32 * XROW) * 4;   // 231,424 B

    cudaFuncSetAttribute(gx_kernel, cudaFuncAttributeMaxDynamicSharedMemorySize, smem1);

    gx_kernel<<<128, 512, smem1>>>(x, W_ih, b_ih);
    gru_kernel<<<128, 768>>>(state, W_hh, b_hh, out);
}